// round 5
// baseline (speedup 1.0000x reference)
#include <cuda_runtime.h>

// Depth-to-space k=3 (CRD order):
//   in:  (B=32, C=9, H=512, W=512) float32
//   out: (B=32, 1, 1536, 1536)     float32
//   out[b, 3i+r, 3j+s] = in[b, 3r+s, i, j]
//
// Thread <-> (b, oy, j):  oy = 3i + r  (output row), j = input column.
// Each thread loads 3 floats (channels 3r+0..2 at same (i,j)) -- loads are
// perfectly coalesced across lanes (consecutive j). It writes 3 consecutive
// output floats at column 3j -- per-instruction lanes stride 12B, but the
// three consecutive STGs fill every 32B sector, so L2 merges to full lines.
//
// Sizes: 32*1536*512 = 25,165,824 threads; plane = 512*512 = 262,144 elems.

__global__ __launch_bounds__(256) void d2s_k3_kernel(
    const float* __restrict__ in, float* __restrict__ out)
{
    int idx = blockIdx.x * blockDim.x + threadIdx.x;   // < 25,165,824

    int j    = idx & 511;        // input column
    int rest = idx >> 9;         // b*1536 + oy
    int oy   = rest % 1536;      // output row within batch
    // b folded into 'rest' for the output offset; need b only for input:
    int b    = rest / 1536;

    int i = oy / 3;              // input row
    int r = oy - 3 * i;          // row-offset within 3x3 cell

    // input base: ((b*9 + 3r) * 512 + i) * 512 + j ; channel step = 262144
    const float* ip = in + ((((b * 9 + r * 3) * 512) + i) << 9) + j;
    float v0 = ip[0];
    float v1 = ip[262144];
    float v2 = ip[524288];

    // output: (b*1536 + oy) * 1536 + 3j
    float* op = out + rest * 1536 + 3 * j;
    op[0] = v0;
    op[1] = v1;
    op[2] = v2;
}

extern "C" void kernel_launch(void* const* d_in, const int* in_sizes, int n_in,
                              void* d_out, int out_size)
{
    const float* in  = (const float*)d_in[0];   // (32,9,512,512) fp32
    float*       out = (float*)d_out;           // 75,497,472 fp32

    // 25,165,824 threads / 256 = 98,304 blocks
    const int threads = 256;
    const int total   = 32 * 1536 * 512;
    const int blocks  = total / threads;

    d2s_k3_kernel<<<blocks, threads>>>(in, out);
}

// round 6
// speedup vs baseline: 1.0418x; 1.0418x over previous
#include <cuda_runtime.h>

// Depth-to-space k=3 (CRD): out[b, 3i+r, 3j+s] = in[b, 3r+s, i, j]
//   in : (32, 9, 512, 512) fp32
//   out: (32, 1, 1536, 1536) fp32
//
// One block per output row (b, oy).  oy = 3i + r.
// Row contents: out[b, oy, 3j+s] = in[b, 3r+s, i, j]  for j in [0,512), s in [0,3).
//
// Phase 1: 384 threads x 4 iters load the 3 channel-rows linearly
//          (consecutive lanes -> consecutive j -> fully coalesced LDG.32),
//          scatter to smem[3j+s]  (word stride 3, gcd(3,32)=1 -> no bank conflicts).
// Phase 2: each thread stores one float4 -> fully coalesced STG.128.
//
// Traffic per block: 6 KB in + 6 KB out, 1 barrier.

#define BLOCK 384          // 12 warps
#define ROW_ELEMS 1536     // output row width = 3*512

__global__ __launch_bounds__(BLOCK) void d2s_k3_smem_kernel(
    const float* __restrict__ in, float* __restrict__ out)
{
    __shared__ float row[ROW_ELEMS];

    const int tid = threadIdx.x;
    const int rb  = blockIdx.x;        // b*1536 + oy
    const int oy  = rb % 1536;
    const int b   = rb / 1536;
    const int i   = oy / 3;
    const int r   = oy - 3 * i;

    // base of channel (3r+0), row i within batch b:
    // ((b*9 + 3r)*512 + i)*512 + j ; channel step = 262144 words
    const float* ip = in + ((((b * 9 + r * 3) * 512) + i) << 9);

    #pragma unroll
    for (int l = 0; l < 4; ++l) {
        int t  = tid + l * BLOCK;      // 0..1535
        int s  = t >> 9;               // source channel offset 0..2
        int jj = t & 511;              // input column
        float v = ip[s * 262144 + jj]; // coalesced: lanes -> consecutive jj
        row[3 * jj + s] = v;           // stride-3 scatter, conflict-free
    }

    __syncthreads();

    // coalesced float4 store of the assembled row
    float4 v4 = reinterpret_cast<const float4*>(row)[tid];
    float4* op = reinterpret_cast<float4*>(out + (long long)rb * ROW_ELEMS);
    op[tid] = v4;
}

extern "C" void kernel_launch(void* const* d_in, const int* in_sizes, int n_in,
                              void* d_out, int out_size)
{
    const float* in  = (const float*)d_in[0];
    float*       out = (float*)d_out;

    const int blocks = 32 * 1536;      // one block per output row
    d2s_k3_smem_kernel<<<blocks, BLOCK>>>(in, out);
}

// round 7
// speedup vs baseline: 1.1982x; 1.1501x over previous
#include <cuda_runtime.h>

// Depth-to-space k=3 (CRD): out[b, 3i+r, 3j+s] = in[b, 3r+s, i, j]
//   in : (32, 9, 512, 512) fp32
//   out: (32, 1, 1536, 1536) fp32
//
// One block per INPUT row (b, i)  ->  3 contiguous output rows (3i, 3i+1, 3i+2).
//
// Phase 1: 9 iterations, one full channel-row each: lane tid loads column tid
//          of channel c (fully coalesced LDG.32, 9 independent loads in flight
//          per thread), scatters to smem[r*1536 + 3*tid + s]  (stride-3 word
//          scatter, gcd(3,32)=1 -> bank-conflict-free).
// Phase 2: the 3 output rows are 18KB CONTIGUOUS in gmem -> pure coalesced
//          float4 streaming stores.
//
// Per block: 18KB in + 18KB out, ONE barrier.  Grid = 32*512 = 16384 blocks.
// 512 thr x 18KB smem -> 4 blocks/SM (thread-limited), full 64-warp occupancy.

#define THREADS 512
#define ROW3 4608            // 3 * 1536 floats = 18KB

__global__ __launch_bounds__(THREADS) void d2s_k3_row3_kernel(
    const float* __restrict__ in, float* __restrict__ out)
{
    __shared__ float rows[ROW3];

    const int tid = threadIdx.x;
    const int bi  = blockIdx.x;        // b*512 + i
    const int i   = bi & 511;
    const int b   = bi >> 9;

    // channel c row base: (b*9 + c)*262144 + i*512
    const float* ip = in + (size_t)b * 9 * 262144 + (size_t)i * 512 + tid;

    #pragma unroll
    for (int c = 0; c < 9; ++c) {
        float v = __ldcs(ip + (size_t)c * 262144);   // coalesced, touch-once
        const int r = c / 3;
        const int s = c - 3 * r;
        rows[r * 1536 + 3 * tid + s] = v;            // conflict-free scatter
    }

    __syncthreads();

    // 18KB contiguous output: rows 3i..3i+2 of batch b
    const float4* rv = reinterpret_cast<const float4*>(rows);
    float4* op = reinterpret_cast<float4*>(
        out + (size_t)(b * 1536 + 3 * i) * 1536);

    __stcs(&op[tid],        rv[tid]);
    __stcs(&op[tid + 512],  rv[tid + 512]);
    if (tid < 128)
        __stcs(&op[tid + 1024], rv[tid + 1024]);
}

extern "C" void kernel_launch(void* const* d_in, const int* in_sizes, int n_in,
                              void* d_out, int out_size)
{
    const float* in  = (const float*)d_in[0];
    float*       out = (float*)d_out;

    d2s_k3_row3_kernel<<<32 * 512, THREADS>>>(in, out);
}

// round 8
// speedup vs baseline: 1.2118x; 1.0114x over previous
#include <cuda_runtime.h>

// Depth-to-space k=3 (CRD): out[b, 3i+r, 3j+s] = in[b, 3r+s, i, j]
//   in : (32, 9, 512, 512) fp32
//   out: (32, 1, 1536, 1536) fp32
//
// One block per INPUT row (b, i) -> 3 contiguous output rows (18KB).
//
// R7 -> R8: 512 -> 256 threads/block. 8 blocks/SM (vs 4): more independent
// barrier domains per SM desynchronizes load/store phases chip-wide (smoother
// DRAM R/W mix), and each thread fronts 18 independent coalesced LDG.32s
// (vs 9) -> deeper per-warp MLP across the phase boundary.
//
// Scatter stays scalar stride-3 (gcd(3,32)=1, bank-conflict-free) -- verified
// L1-optimal: float4 loads would force a stride-12 scatter (4-way conflicts)
// and flip the bottleneck to L1.

#define THREADS 256
#define ROW3 4608            // 3 * 1536 floats = 18KB

__global__ __launch_bounds__(THREADS) void d2s_k3_row3_b256_kernel(
    const float* __restrict__ in, float* __restrict__ out)
{
    __shared__ float rows[ROW3];

    const int tid = threadIdx.x;
    const int bi  = blockIdx.x;        // b*512 + i
    const int i   = bi & 511;
    const int b   = bi >> 9;

    // base of (batch b, input row i), channel 0
    const float* ip = in + (size_t)b * 9 * 262144 + (size_t)i * 512;

    // 18 fully-coalesced, independent streaming loads per thread
    #pragma unroll
    for (int l = 0; l < 18; ++l) {
        int t   = tid + l * THREADS;   // 0..4607
        int c   = t >> 9;              // channel 0..8
        int col = t & 511;             // input column
        float v = __ldcs(ip + c * 262144 + col);
        int r = c / 3;
        int s = c - 3 * r;
        rows[r * 1536 + 3 * col + s] = v;   // conflict-free stride-3 scatter
    }

    __syncthreads();

    // 18KB contiguous output: rows 3i..3i+2 of batch b, coalesced float4
    const float4* rv = reinterpret_cast<const float4*>(rows);
    float4* op = reinterpret_cast<float4*>(
        out + (size_t)(b * 1536 + 3 * i) * 1536);

    #pragma unroll
    for (int l = 0; l < 4; ++l)
        __stcs(&op[tid + l * THREADS], rv[tid + l * THREADS]);
    if (tid < 128)
        __stcs(&op[tid + 1024], rv[tid + 1024]);
}

extern "C" void kernel_launch(void* const* d_in, const int* in_sizes, int n_in,
                              void* d_out, int out_size)
{
    const float* in  = (const float*)d_in[0];
    float*       out = (float*)d_out;

    d2s_k3_row3_b256_kernel<<<32 * 512, THREADS>>>(in, out);
}